// round 2
// baseline (speedup 1.0000x reference)
#include <cuda_runtime.h>
#include <cuda_bf16.h>
#include <cstdint>

#define BATCH       64
#define SIZE        224
#define PIXELS      (SIZE*SIZE)        // 50176
#define DIM         40
#define NUM_CLASSES 10
#define WORDS       (PIXELS/32)        // 1568 (exact)
#define GEMM_ITERS  (WORDS/32)         // 49 (exact: 1568 = 49*32)
#define NBX         256                // blocks for x-pack
#define NBQ         (PIXELS/256)       // 196 blocks for pos-pack (256 px each)

// Scratch: packed mask bits per batch, packed sign bits per dim.
__device__ uint32_t g_M[BATCH * WORDS];   // 401 KB
__device__ uint32_t g_Q[DIM * WORDS];     // 251 KB

// ---------------------------------------------------------------------------
// Kernel 1: bit-pack. Blocks [0, NBX) pack x > 0.5 into g_M (coalesced loads +
// warp ballot). Blocks [NBX, NBX+NBQ) transpose a 256x40 tile of pos through
// shared memory (pitch 41 -> conflict-free column reads) and ballot pos > 0
// into g_Q.
//
// Note on exactness: NUM_LEVELS=2 means idx = round(x); jnp.round is
// half-to-even so idx=1  <=>  x > 0.5 strictly. pos/level are {-1,+1}, so
// all sums up to `enc` are exact integers in both this kernel and the
// reference's fp32 arithmetic (magnitudes << 2^24) -> enc matches exactly.
// ---------------------------------------------------------------------------
__global__ void __launch_bounds__(256)
pack_kernel(const float* __restrict__ x,
            const float* __restrict__ pos) {
    const int lane = threadIdx.x & 31;
    const int wid  = threadIdx.x >> 5;

    if (blockIdx.x < NBX) {
        // ---- mask pack: one 32-pixel word per warp-iteration ----
        const int warps_per_block = blockDim.x >> 5;
        const int gwarp  = blockIdx.x * warps_per_block + wid;
        const int nwarps = NBX * warps_per_block;
        const int total_words = BATCH * WORDS;   // 100352
        for (int w = gwarp; w < total_words; w += nwarps) {
            float v = x[(size_t)w * 32 + lane];          // fully coalesced
            unsigned m = __ballot_sync(0xffffffffu, v > 0.5f);
            if (lane == 0) g_M[w] = m;
        }
    } else {
        // ---- pos pack: block handles 256 pixels (8 words per dim) ----
        __shared__ float tile[256 * 41];                 // pitch 41: no conflicts
        const int p0 = (blockIdx.x - NBX) * 256;
        for (int i = threadIdx.x; i < 256 * DIM; i += blockDim.x) {
            int p = i / DIM, d = i % DIM;
            tile[p * 41 + d] = pos[(size_t)(p0 + p) * DIM + d];  // coalesced
        }
        __syncthreads();
        // 40 dims x 8 words = 320 ballots, warp-strided (uniform per warp)
        for (int t = wid; t < DIM * 8; t += 8) {
            int d = t >> 3, j = t & 7;
            float v = tile[(j * 32 + lane) * 41 + d];    // stride 41: conflict-free
            unsigned m = __ballot_sync(0xffffffffu, v > 0.0f);
            if (lane == 0) g_Q[d * WORDS + (p0 >> 5) + j] = m;
        }
    }
}

// ---------------------------------------------------------------------------
// Kernel 2: one block per batch. Binary GEMM via popcount, exact integer
// epilogue (summed -> sign), then the 10x40 classify dot. Q streams from L2
// (read by all 64 blocks -> stays hot), M row lives in shared.
// ---------------------------------------------------------------------------
__global__ void __launch_bounds__(256)
hdc_gemm_kernel(const float* __restrict__ lvl,   // [2, DIM]
                const float* __restrict__ cls,   // [10, DIM]
                float* __restrict__ out) {       // [BATCH, 10]
    const int b    = blockIdx.x;
    const int lane = threadIdx.x & 31;
    const int wid  = threadIdx.x >> 5;      // 8 warps

    __shared__ uint32_t Ms[WORDS];
    __shared__ int  sAnd[DIM];
    __shared__ int  sQ[DIM];
    __shared__ float enc[DIM];
    __shared__ int  sC;

    if (threadIdx.x == 0) sC = 0;
    __syncthreads();

    // Load mask row + count set bits (C_b = #pixels with x>0.5)
    const uint32_t* __restrict__ Mrow = &g_M[b * WORDS];
    int cpart = 0;
    for (int i = threadIdx.x; i < WORDS; i += blockDim.x) {
        uint32_t m = Mrow[i];
        Ms[i] = m;
        cpart += __popc(m);
    }
    cpart = __reduce_add_sync(0xffffffffu, cpart);
    if (lane == 0) atomicAdd(&sC, cpart);
    __syncthreads();

    // Main binary GEMM: warp 'wid' covers dims wid, wid+8, ... (5 dims/warp).
    // Each lane strides the 1568 words (1568 = 49*32, uniform full warp,
    // compile-time trip count 49).
    for (int d = wid; d < DIM; d += 8) {
        const uint32_t* __restrict__ Qd = &g_Q[d * WORDS];
        int aAnd = 0, aQ = 0;
        #pragma unroll 7
        for (int it = 0; it < GEMM_ITERS; it++) {
            int i = it * 32 + lane;
            uint32_t q = Qd[i];
            aAnd += __popc(q & Ms[i]);
            aQ   += __popc(q);
        }
        aAnd = __reduce_add_sync(0xffffffffu, aAnd);
        aQ   = __reduce_add_sync(0xffffffffu, aQ);
        if (lane == 0) { sAnd[d] = aAnd; sQ[d] = aQ; }
    }
    __syncthreads();

    // Exact integer epilogue -> hard_quantize sign
    if (threadIdx.x < DIM) {
        int d   = threadIdx.x;
        int C   = sC;
        int A   = 2 * sAnd[d] - C;        // sum of pos over masked pixels
        int Tot = 2 * sQ[d]   - PIXELS;   // sum of pos over all pixels
        float L0 = lvl[d], L1 = lvl[DIM + d];
        float summed = L0 * (float)(Tot - A) + L1 * (float)A;   // exact ints
        enc[d] = (summed > 0.0f) ? 1.0f : -1.0f;
    }
    __syncthreads();

    // Classify: logits[c] = sum_d enc[d] * W[c,d]
    if (threadIdx.x < NUM_CLASSES) {
        int c = threadIdx.x;
        float acc = 0.0f;
        #pragma unroll
        for (int d = 0; d < DIM; d++) acc += enc[d] * cls[c * DIM + d];
        out[b * NUM_CLASSES + c] = acc;
    }
}

// ---------------------------------------------------------------------------
extern "C" void kernel_launch(void* const* d_in, const int* in_sizes, int n_in,
                              void* d_out, int out_size) {
    const float* x   = (const float*)d_in[0];   // [64, 224, 224]
    const float* pos = (const float*)d_in[1];   // [50176, 40]
    const float* lvl = (const float*)d_in[2];   // [2, 40]
    const float* cls = (const float*)d_in[3];   // [10, 40]
    float* out = (float*)d_out;                 // [64, 10]

    pack_kernel<<<NBX + NBQ, 256>>>(x, pos);
    hdc_gemm_kernel<<<BATCH, 256>>>(lvl, cls, out);
}

// round 4
// speedup vs baseline: 1.3360x; 1.3360x over previous
#include <cuda_runtime.h>
#include <cstdint>

#define BATCH       64
#define SIZE        224
#define PIXELS      (SIZE*SIZE)        // 50176
#define DIM         40
#define NUM_CLASSES 10
#define WORDS       (PIXELS/32)        // 1568
#define NCHUNK      7                  // word chunks in main kernel
#define CW          (WORDS/NCHUNK)     // 224 words per chunk (exact)
#define QPITCH      225                // 224+1: conflict-free lane*QPITCH strides
#define NBQ         (PIXELS/256)       // 196 pos-pack blocks (256 px each)

// Packed pos sign bits per dim, and deterministic partial accumulators
// (every slot written every launch -> no zeroing, no global atomics).
__device__ uint32_t g_Q[DIM * WORDS];            // 251 KB
__device__ int      g_TotPart[NBQ * DIM];        // per-pos-block popc(Q) partials
__device__ int      g_Part[NCHUNK * BATCH * DIM];// per (chunk,b) AND-popc partials
__device__ int      g_CPart[NCHUNK * BATCH];     // per (chunk,b) popc(M) partials

// ---------------------------------------------------------------------------
// Kernel A: pack pos>0 into g_Q (shared-tile transpose, pitch 41) and emit
// per-block popcount partials for Tot[d].
// Exactness: pos/level are exactly {-1,+1}; NUM_LEVELS=2 -> idx=round(x) with
// half-to-even so level-1 <=> x>0.5 strictly. All sums to `enc` are exact
// integers in both this kernel and the reference fp32 math.
// ---------------------------------------------------------------------------
__global__ void __launch_bounds__(256)
pack_pos_kernel(const float* __restrict__ pos) {
    __shared__ float tile[256 * 41];
    __shared__ int   sTot[DIM];
    const int tid  = threadIdx.x;
    const int lane = tid & 31;
    const int wid  = tid >> 5;

    if (tid < DIM) sTot[tid] = 0;
    const int p0 = blockIdx.x * 256;
    for (int i = tid; i < 256 * DIM; i += 256) {
        int p = i / DIM, d = i % DIM;
        tile[p * 41 + d] = pos[(size_t)(p0 + p) * DIM + d];   // coalesced
    }
    __syncthreads();

    for (int t = wid; t < DIM * 8; t += 8) {       // 40 dims x 8 words
        int d = t >> 3, j = t & 7;
        float v = tile[(j * 32 + lane) * 41 + d];  // stride 41: conflict-free
        unsigned m = __ballot_sync(0xffffffffu, v > 0.0f);
        if (lane == 0) {
            g_Q[d * WORDS + (p0 >> 5) + j] = m;
            atomicAdd(&sTot[d], __popc(m));        // shared atomic, cheap
        }
    }
    __syncthreads();
    if (tid < DIM) g_TotPart[blockIdx.x * DIM + tid] = sTot[tid];
}

// ---------------------------------------------------------------------------
// Kernel B: fused mask-pack + binary GEMM. Block = (chunk c, batch b).
// Warp ballots x>0.5 on coalesced loads, ANDs with the shared Q chunk;
// per-lane accumulators (dim = lane) -> no cross-lane reduction in the loop.
// ---------------------------------------------------------------------------
__global__ void __launch_bounds__(256)
main_kernel(const float* __restrict__ x) {
    const int c = blockIdx.x >> 6;     // 0..6 (same-chunk blocks adjacent -> Q L2-hot)
    const int b = blockIdx.x & 63;
    const int tid  = threadIdx.x;
    const int lane = tid & 31;
    const int wid  = tid >> 5;

    __shared__ uint32_t sQ[DIM * QPITCH];
    __shared__ int sAcc[DIM];
    __shared__ int sCacc;

    if (tid < DIM) sAcc[tid] = 0;
    if (tid == 0)  sCacc = 0;

    const int w0 = c * CW;
    for (int i = tid; i < DIM * CW; i += 256) {
        int d = i / CW, j = i % CW;
        sQ[d * QPITCH + j] = g_Q[d * WORDS + w0 + j];   // L2-hot after first b
    }
    __syncthreads();

    // Warp 'wid' covers words [wid*28, wid*28+28) of this chunk.
    const float* __restrict__ xb = x + (size_t)b * PIXELS + (size_t)w0 * 32;
    const int jbase = wid * (CW / 8);                   // 28 words/warp
    int acc0 = 0, acc1 = 0, accC = 0;
    #pragma unroll 4
    for (int jj = 0; jj < CW / 8; jj++) {
        int j = jbase + jj;
        float v = xb[j * 32 + lane];                    // 128B coalesced
        unsigned m = __ballot_sync(0xffffffffu, v > 0.5f);
        accC += __popc(m);
        uint32_t q0 = sQ[lane * QPITCH + j];            // dim = lane
        acc0 += __popc(m & q0);
        if (lane < 8) {
            uint32_t q1 = sQ[(lane + 32) * QPITCH + j]; // dims 32..39
            acc1 += __popc(m & q1);
        }
    }
    atomicAdd(&sAcc[lane], acc0);
    if (lane < 8) atomicAdd(&sAcc[lane + 32], acc1);
    if (lane == 0) atomicAdd(&sCacc, accC);
    __syncthreads();

    if (tid < DIM) g_Part[blockIdx.x * DIM + tid] = sAcc[tid];
    if (tid == 0)  g_CPart[blockIdx.x] = sCacc;
}

// ---------------------------------------------------------------------------
// Kernel C: single-block reduction + exact integer epilogue + classify.
// ---------------------------------------------------------------------------
__global__ void __launch_bounds__(1024)
epilogue_kernel(const float* __restrict__ lvl,   // [2, DIM]
                const float* __restrict__ cls,   // [10, DIM]
                float* __restrict__ out) {       // [BATCH, 10]
    __shared__ int   sTot[DIM];
    __shared__ int   sC[BATCH];
    __shared__ int   sA[BATCH * DIM];
    __shared__ float enc[BATCH * DIM];
    const int tid = threadIdx.x;

    if (tid < DIM) sTot[tid] = 0;
    __syncthreads();

    // Tot[d]: reduce 196 partials, 25 groups x 40 dims = 1000 threads
    if (tid < 1000) {
        int d = tid % DIM, g = tid / DIM;
        int s = 0;
        for (int k = g; k < NBQ; k += 25) s += g_TotPart[k * DIM + d];
        atomicAdd(&sTot[d], s);
    }
    // AND partials: 2560 (b,d) pairs, 7 chunks each
    for (int p = tid; p < BATCH * DIM; p += 1024) {
        int b = p / DIM, d = p % DIM;
        int s = 0;
        #pragma unroll
        for (int c = 0; c < NCHUNK; c++) s += g_Part[(c * BATCH + b) * DIM + d];
        sA[p] = s;
    }
    if (tid < BATCH) {
        int s = 0;
        #pragma unroll
        for (int c = 0; c < NCHUNK; c++) s += g_CPart[c * BATCH + tid];
        sC[tid] = s;
    }
    __syncthreads();

    // Exact integer epilogue -> hard_quantize sign
    for (int p = tid; p < BATCH * DIM; p += 1024) {
        int b = p / DIM, d = p % DIM;
        int A   = 2 * sA[p]   - sC[b];      // sum of pos over masked pixels
        int Tot = 2 * sTot[d] - PIXELS;     // sum of pos over all pixels
        float summed = lvl[d] * (float)(Tot - A) + lvl[DIM + d] * (float)A;
        enc[p] = (summed > 0.0f) ? 1.0f : -1.0f;
    }
    __syncthreads();

    // logits[b][c] = sum_d enc[b][d] * W[c][d]
    if (tid < BATCH * NUM_CLASSES) {
        int b = tid / NUM_CLASSES, c = tid % NUM_CLASSES;
        float acc = 0.0f;
        #pragma unroll
        for (int d = 0; d < DIM; d++) acc += enc[b * DIM + d] * cls[c * DIM + d];
        out[tid] = acc;
    }
}

// ---------------------------------------------------------------------------
extern "C" void kernel_launch(void* const* d_in, const int* in_sizes, int n_in,
                              void* d_out, int out_size) {
    const float* x   = (const float*)d_in[0];   // [64, 224, 224]
    const float* pos = (const float*)d_in[1];   // [50176, 40]
    const float* lvl = (const float*)d_in[2];   // [2, 40]
    const float* cls = (const float*)d_in[3];   // [10, 40]
    float* out = (float*)d_out;                 // [64, 10]

    pack_pos_kernel<<<NBQ, 256>>>(pos);
    main_kernel<<<NCHUNK * BATCH, 256>>>(x);
    epilogue_kernel<<<1, 1024>>>(lvl, cls, out);
}